// round 8
// baseline (speedup 1.0000x reference)
#include <cuda_runtime.h>
#include <math.h>

#define Bb 256
#define Tt 256
#define Dd 64
#define Hh 512

typedef unsigned long long ull;

// Scratch (device globals: allocation-free rule).
__device__ float g_xp[(size_t)Bb * Tt * Hh];
__device__ float g_h [(size_t)Bb * Tt * Hh];
__device__ float g_hx[2 * Bb * Hh];      // 1MB L2-hot exchange buffer (double)
__device__ int   g_bar[3 * 16];          // per (layer, 16-row group) counters

// ---------------- packed dual-fp32 helpers (sm_100+ f32x2) ----------------
__device__ __forceinline__ ull fma2(ull a, ull b, ull c) {
    ull d;
    asm("fma.rn.f32x2 %0, %1, %2, %3;" : "=l"(d) : "l"(a), "l"(b), "l"(c));
    return d;
}
__device__ __forceinline__ ull dup2(float x) {
    ull d;
    asm("mov.b64 %0, {%1, %2};" : "=l"(d) : "f"(x), "f"(x));
    return d;
}
__device__ __forceinline__ float2 unpack2(ull v) {
    float2 r;
    asm("mov.b64 {%0, %1}, %2;" : "=f"(r.x), "=f"(r.y) : "l"(v));
    return r;
}
__device__ __forceinline__ int ld_acquire(const int* p) {
    int v;
    asm volatile("ld.acquire.gpu.global.b32 %0, [%1];" : "=r"(v) : "l"(p));
    return v;
}
__device__ __forceinline__ void red_release_add(int* p, int v) {
    asm volatile("red.release.gpu.global.add.s32 [%0], %1;" :: "l"(p), "r"(v) : "memory");
}
__device__ __forceinline__ float fast_tanh(float x) {
    float ax = fabsf(x);
    float e;
    asm("ex2.approx.f32 %0, %1;" : "=f"(e) : "f"(ax * 2.885390082f));
    float t = 1.0f - __fdividef(2.0f, e + 1.0f);
    return copysignf(t, x);
}

__global__ void zero_bar_kernel() {
    if (threadIdx.x < 48) g_bar[threadIdx.x] = 0;
}

// ---------------------------------------------------------------------------
// Projection GEMM: out[M,Hh] = A[M,K] @ W[K,Hh] + bias    (M = Bb*Tt)
// Tile 128x128, BK=16, 256 threads, thread tile 8x8 via f32x2.  (proven)
// ---------------------------------------------------------------------------
template <int K>
__global__ __launch_bounds__(256) void proj_kernel(
    const float* __restrict__ A, const float* __restrict__ W,
    const float* __restrict__ bias, float* __restrict__ out)
{
    __shared__ float sA[16 * 132];
    __shared__ float sB[16 * 128];

    const int n0 = blockIdx.x * 128;
    const int m0 = blockIdx.y * 128;
    const int tid = threadIdx.x;
    const int tx = tid & 15;
    const int ty = tid >> 4;

    const int arow = tid >> 1;
    const int ak   = (tid & 1) * 8;
    const int bk   = tid >> 4;
    const int bc   = (tid & 15) * 8;

    ull acc[8][4];
#pragma unroll
    for (int i = 0; i < 8; i++)
#pragma unroll
        for (int j = 0; j < 4; j++) acc[i][j] = 0ull;

    float4 va0 = *(const float4*)&A[(size_t)(m0 + arow) * K + ak];
    float4 va1 = *(const float4*)&A[(size_t)(m0 + arow) * K + ak + 4];
    float4 vb0 = *(const float4*)&W[(size_t)bk * Hh + n0 + bc];
    float4 vb1 = *(const float4*)&W[(size_t)bk * Hh + n0 + bc + 4];

    const int NB = K / 16;
    for (int kb = 0; kb < NB; kb++) {
        sA[(ak + 0) * 132 + arow] = va0.x;
        sA[(ak + 1) * 132 + arow] = va0.y;
        sA[(ak + 2) * 132 + arow] = va0.z;
        sA[(ak + 3) * 132 + arow] = va0.w;
        sA[(ak + 4) * 132 + arow] = va1.x;
        sA[(ak + 5) * 132 + arow] = va1.y;
        sA[(ak + 6) * 132 + arow] = va1.z;
        sA[(ak + 7) * 132 + arow] = va1.w;
        *(float4*)&sB[bk * 128 + bc]     = vb0;
        *(float4*)&sB[bk * 128 + bc + 4] = vb1;
        __syncthreads();

        if (kb + 1 < NB) {
            int k0 = (kb + 1) * 16;
            va0 = *(const float4*)&A[(size_t)(m0 + arow) * K + k0 + ak];
            va1 = *(const float4*)&A[(size_t)(m0 + arow) * K + k0 + ak + 4];
            vb0 = *(const float4*)&W[(size_t)(k0 + bk) * Hh + n0 + bc];
            vb1 = *(const float4*)&W[(size_t)(k0 + bk) * Hh + n0 + bc + 4];
        }

#pragma unroll
        for (int kk = 0; kk < 16; kk++) {
            float4 a0 = *(const float4*)&sA[kk * 132 + ty * 8];
            float4 a1 = *(const float4*)&sA[kk * 132 + ty * 8 + 4];
            ulonglong2 b0 = *(const ulonglong2*)&sB[kk * 128 + tx * 8];
            ulonglong2 b1 = *(const ulonglong2*)&sB[kk * 128 + tx * 8 + 4];
            float ar[8] = {a0.x, a0.y, a0.z, a0.w, a1.x, a1.y, a1.z, a1.w};
#pragma unroll
            for (int r = 0; r < 8; r++) {
                ull av = dup2(ar[r]);
                acc[r][0] = fma2(av, b0.x, acc[r][0]);
                acc[r][1] = fma2(av, b0.y, acc[r][1]);
                acc[r][2] = fma2(av, b1.x, acc[r][2]);
                acc[r][3] = fma2(av, b1.y, acc[r][3]);
            }
        }
        __syncthreads();
    }

    float4 bi0 = *(const float4*)&bias[n0 + tx * 8];
    float4 bi1 = *(const float4*)&bias[n0 + tx * 8 + 4];
#pragma unroll
    for (int r = 0; r < 8; r++) {
        float2 u0 = unpack2(acc[r][0]);
        float2 u1 = unpack2(acc[r][1]);
        float2 u2 = unpack2(acc[r][2]);
        float2 u3 = unpack2(acc[r][3]);
        float4 o0, o1;
        o0.x = u0.x + bi0.x; o0.y = u0.y + bi0.y; o0.z = u1.x + bi0.z; o0.w = u1.y + bi0.w;
        o1.x = u2.x + bi1.x; o1.y = u2.y + bi1.y; o1.z = u3.x + bi1.z; o1.w = u3.y + bi1.w;
        size_t base = (size_t)(m0 + ty * 8 + r) * Hh + n0 + tx * 8;
        *(float4*)&out[base]     = o0;
        *(float4*)&out[base + 4] = o1;
    }
}

// ---------------------------------------------------------------------------
// Persistent layer kernel, occupancy-2.
// Grid (16 col-tiles of 32 x 16 groups of 16 rows) = 256 CTAs, 2 per SM.
// Warp = (k-chunk 0..3 of 128k, row-half 0..1 of 8 rows); lane tile
// 2 rows x 4 cols over 128 k.  4-way smem reduction.
// ---------------------------------------------------------------------------
#define NC      32
#define SH_STR  516
#define RED_STR 34
#define SW_F    (512 * NC)               // 16384 floats
#define SH_F    (16 * SH_STR)            // 8256
#define RED_F   (4 * 16 * RED_STR)       // 2176
#define LAYER_SMEM ((SW_F + SH_F + RED_F) * 4)    // 107264 B

extern __shared__ float s_mem[];

__global__ __launch_bounds__(256, 2) void layer_kernel(
    const float* __restrict__ xp, const float* __restrict__ Wh,
    float* __restrict__ h, float* __restrict__ hx,
    int* __restrict__ bar, int layer)
{
    float* sW   = s_mem;                      // [512][32]
    float* sH   = s_mem + SW_F;               // [16][516]
    float* sRed = s_mem + SW_F + SH_F;        // [4][16][34]

    const int n0 = blockIdx.x * NC;
    const int b0 = blockIdx.y * 16;
    int* cnt = &bar[layer * 16 + blockIdx.y];

    const int tid  = threadIdx.x;
    const int w    = tid >> 5;
    const int lane = tid & 31;
    const int kc   = w >> 1;             // k-chunk (128 k)
    const int rh   = w & 1;              // row half (8 rows)
    const int rr   = lane >> 3;          // row pair within half (2 rows)
    const int cg   = lane & 7;           // col group of 4
    const int kbase = kc * 128;
    const int row0  = rh * 8 + rr * 2;

    const int er = tid >> 4;             // epilogue row 0..15
    const int ec = (tid & 15) * 2;       // epilogue col (float2)

    // ---- stage Wh[:, n0:n0+32] once ----
    for (int i = tid; i < 512 * 8; i += 256) {
        int k = i >> 3, c4 = i & 7;
        float4 v = *(const float4*)&Wh[(size_t)k * Hh + n0 + c4 * 4];
        *(float4*)&sW[k * NC + c4 * 4] = v;
    }

    // ---- t = 0: h0 = tanh(xp0) ----
    {
        size_t base = ((size_t)(b0 + er) * Tt) * Hh + n0 + ec;
        float2 xv = *(const float2*)&xp[base];
        float2 o;
        o.x = fast_tanh(xv.x); o.y = fast_tanh(xv.y);
        *(float2*)&h[base] = o;
        __stcg((float2*)&hx[(size_t)(b0 + er) * Hh + n0 + ec], o);
    }
    __syncthreads();                 // sW staged + h0 issued
    if (tid == 0) red_release_add(cnt, 1);

    for (int t = 1; t < Tt; t++) {
        // prefetch xp for this step (independent of the flag)
        size_t obase = (((size_t)(b0 + er) * Tt) + t) * Hh + n0 + ec;
        float2 xv = *(const float2*)&xp[obase];

        // ---- wait for all 16 producers of h_{t-1} ----
        if (tid == 0) {
            while (ld_acquire(cnt) < 16 * t) { }
        }
        __syncthreads();

        // ---- CTA-cooperative stage of hx[(t-1)&1] rows b0..b0+15 ----
        {
            const float* src = hx + ((size_t)((t - 1) & 1)) * (Bb * Hh);
            float4 sv[8];
#pragma unroll
            for (int j = 0; j < 8; j++) {
                int slot = tid + j * 256;
                int r = slot >> 7, k4 = slot & 127;
                sv[j] = __ldcg((const float4*)&src[(size_t)(b0 + r) * Hh + k4 * 4]);
            }
#pragma unroll
            for (int j = 0; j < 8; j++) {
                int slot = tid + j * 256;
                int r = slot >> 7, k4 = slot & 127;
                *(float4*)&sH[r * SH_STR + k4 * 4] = sv[j];
            }
        }
        __syncthreads();

        // ---- compute: warp (kc,rh): rows row0..row0+1, 32 cols, 128 k ----
        ull a00 = 0, a01 = 0, a10 = 0, a11 = 0;
        {
            const float* hp0 = &sH[row0 * SH_STR + kbase];
            const float* hp1 = &sH[(row0 + 1) * SH_STR + kbase];
            const float* wp  = &sW[kbase * NC];
#pragma unroll 8
            for (int kk = 0; kk < 128; kk += 4) {
                float4 h0 = *(const float4*)&hp0[kk];
                float4 h1 = *(const float4*)&hp1[kk];
                ulonglong2 w0 = *(const ulonglong2*)&wp[(kk + 0) * NC + cg * 4];
                ulonglong2 w1 = *(const ulonglong2*)&wp[(kk + 1) * NC + cg * 4];
                ulonglong2 w2 = *(const ulonglong2*)&wp[(kk + 2) * NC + cg * 4];
                ulonglong2 w3 = *(const ulonglong2*)&wp[(kk + 3) * NC + cg * 4];
                ull a;
                a = dup2(h0.x); a00 = fma2(a, w0.x, a00); a01 = fma2(a, w0.y, a01);
                a = dup2(h1.x); a10 = fma2(a, w0.x, a10); a11 = fma2(a, w0.y, a11);
                a = dup2(h0.y); a00 = fma2(a, w1.x, a00); a01 = fma2(a, w1.y, a01);
                a = dup2(h1.y); a10 = fma2(a, w1.x, a10); a11 = fma2(a, w1.y, a11);
                a = dup2(h0.z); a00 = fma2(a, w2.x, a00); a01 = fma2(a, w2.y, a01);
                a = dup2(h1.z); a10 = fma2(a, w2.x, a10); a11 = fma2(a, w2.y, a11);
                a = dup2(h0.w); a00 = fma2(a, w3.x, a00); a01 = fma2(a, w3.y, a01);
                a = dup2(h1.w); a10 = fma2(a, w3.x, a10); a11 = fma2(a, w3.y, a11);
            }
        }

        // ---- store partials ----
        {
            float* dst = &sRed[kc * (16 * RED_STR) + row0 * RED_STR + cg * 4];
            *(ull*)&dst[0] = a00;
            *(ull*)&dst[2] = a01;
            *(ull*)&dst[RED_STR] = a10;
            *(ull*)&dst[RED_STR + 2] = a11;
        }
        __syncthreads();

        // ---- reduce 4 partials, add xp, tanh, store h_t ----
        {
            float2 s = make_float2(0.f, 0.f);
            int rb = er * RED_STR + ec;
#pragma unroll
            for (int q = 0; q < 4; q++) {
                float2 u = unpack2(*(const ull*)&sRed[q * (16 * RED_STR) + rb]);
                s.x += u.x; s.y += u.y;
            }
            float2 o;
            o.x = fast_tanh(s.x + xv.x);
            o.y = fast_tanh(s.y + xv.y);
            *(float2*)&h[obase] = o;
            __stcg((float2*)&hx[((size_t)(t & 1)) * (Bb * Hh)
                                + (size_t)(b0 + er) * Hh + n0 + ec], o);
        }
        __syncthreads();   // stores issued before release
        if (tid == 0 && t < Tt - 1) red_release_add(cnt, 1);
    }
}

// ---------------------------------------------------------------------------
// Final: out[b] = h[b, T-1, :] @ Wf + bf
// ---------------------------------------------------------------------------
__global__ void final_kernel(const float* __restrict__ h, const float* __restrict__ Wf,
                             const float* __restrict__ bf, float* __restrict__ out)
{
    int b = blockIdx.x;
    const float* row = h + ((size_t)b * Tt + (Tt - 1)) * Hh;
    float s = 0.f;
    for (int j = threadIdx.x; j < Hh; j += 128) s += row[j] * Wf[j];
#pragma unroll
    for (int o = 16; o > 0; o >>= 1) s += __shfl_down_sync(0xffffffffu, s, o);
    __shared__ float ws[4];
    if ((threadIdx.x & 31) == 0) ws[threadIdx.x >> 5] = s;
    __syncthreads();
    if (threadIdx.x == 0) out[b] = ws[0] + ws[1] + ws[2] + ws[3] + bf[0];
}

// ---------------------------------------------------------------------------
extern "C" void kernel_launch(void* const* d_in, const int* in_sizes, int n_in,
                              void* d_out, int out_size)
{
    const float* x   = (const float*)d_in[0];
    const float* Wx0 = (const float*)d_in[1];
    const float* Wh0 = (const float*)d_in[2];
    const float* b0  = (const float*)d_in[3];
    const float* Wx1 = (const float*)d_in[4];
    const float* Wh1 = (const float*)d_in[5];
    const float* b1  = (const float*)d_in[6];
    const float* Wx2 = (const float*)d_in[7];
    const float* Wh2 = (const float*)d_in[8];
    const float* b2  = (const float*)d_in[9];
    const float* Wf  = (const float*)d_in[10];
    const float* bf  = (const float*)d_in[11];
    float* out = (float*)d_out;

    void* p;
    cudaGetSymbolAddress(&p, g_xp);
    float* xp = (float*)p;
    cudaGetSymbolAddress(&p, g_h);
    float* hb = (float*)p;
    cudaGetSymbolAddress(&p, g_hx);
    float* hx = (float*)p;
    cudaGetSymbolAddress(&p, g_bar);
    int* bar = (int*)p;

    cudaFuncSetAttribute(layer_kernel, cudaFuncAttributeMaxDynamicSharedMemorySize, LAYER_SMEM);

    dim3 pgrid(Hh / 128, (Bb * Tt) / 128);   // (4, 512)
    dim3 lgrid(Hh / NC, Bb / 16);            // (16, 16) = 256 CTAs, 2/SM

    zero_bar_kernel<<<1, 64>>>();

    proj_kernel<Dd><<<pgrid, 256>>>(x, Wx0, b0, xp);
    layer_kernel<<<lgrid, 256, LAYER_SMEM>>>(xp, Wh0, hb, hx, bar, 0);

    proj_kernel<Hh><<<pgrid, 256>>>(hb, Wx1, b1, xp);
    layer_kernel<<<lgrid, 256, LAYER_SMEM>>>(xp, Wh1, hb, hx, bar, 1);

    proj_kernel<Hh><<<pgrid, 256>>>(hb, Wx2, b2, xp);
    layer_kernel<<<lgrid, 256, LAYER_SMEM>>>(xp, Wh2, hb, hx, bar, 2);

    final_kernel<<<Bb, 128>>>(hb, Wf, bf, out);
}